// round 14
// baseline (speedup 1.0000x reference)
#include <cuda_runtime.h>
#include <cstdint>

// Problem constants (fixed by the dataset: N=32768, D=50, P=2)
constexpr int D     = 50;
constexpr int NB    = 1326;          // number of basis functions
constexpr int NPAIR = NB / 2;        // 663 : thread handles adjacent bases (2q, 2q+1)
constexpr int TPB   = 256;
constexpr int RB    = 16;            // rows of x per block
constexpr int PVW   = 52;            // padded width of one pv order row
constexpr int PVR   = 3 * PVW;       // floats per row in pv table (156)

// Analytic decode of the reference _indexset(50, p<=2) layout.
// Returns the two pv offsets (order*PVW + dim) for basis b; identity term = 0
// (pv[order 0][dim 0] == B[0,0] == 1.0).
//
// Layout (concat of indexset(50,0), indexset(50,1), indexset(50,2)):
//   b = 0        : zero multi-index
//   b in [1,50]  : order 1 at dim (50 - b)
//   b in [51,..] : k = b-51 indexes indexset(50,2):
//     m* = largest m with T(m)=m(m+1)/2 <= k ; t = 49-m* ; rem = k-T(m*)
//     rem < m*  -> order-1 at dims (t, 49-rem)
//     rem == m* -> order-2 at dim t
__device__ __forceinline__ void decode_basis(int b, int& offA, int& offB) {
    if (b == 0)       { offA = 0;                  offB = 0; return; }
    if (b <= D)       { offA = PVW + (D - b);      offB = 0; return; }
    int k = b - (D + 1);
    int m = (int)((sqrtf(8.0f * (float)k + 1.0f) - 1.0f) * 0.5f);
    while ((m + 1) * (m + 2) / 2 <= k) ++m;   // fixup for sqrt rounding
    while (m * (m + 1) / 2 > k) --m;
    int t   = (D - 1) - m;
    int rem = k - m * (m + 1) / 2;
    if (rem < m) { offA = PVW + t;     offB = PVW + ((D - 1) - rem); }
    else         { offA = 2 * PVW + t; offB = 0; }
}

__global__ __launch_bounds__(TPB)
void pce_phi_kernel(const float* __restrict__ x,
                    const float* __restrict__ mean,
                    const float* __restrict__ var,
                    const float* __restrict__ Bc,   // oneDbasis (3,3) row-major
                    float* __restrict__ out,
                    int N) {
    __shared__ float pv[RB * PVR];   // [row][order][dim], 9984 B

    const int tid  = threadIdx.x;
    const int row0 = blockIdx.x * RB;
    const int rows = min(RB, N - row0);

    // Per-thread basis-pair term offsets, decoded analytically (no global table).
    // Slot 0: q = tid         (always valid)
    // Slot 1: q = tid + 256   (always valid)
    // Slot 2: q = tid + 512   (valid iff tid < 663 - 512 = 151)
    const bool has2 = (tid < NPAIR - 2 * TPB);

    int oa0_0, ob0_0, oa1_0, ob1_0;
    int oa0_1, ob0_1, oa1_1, ob1_1;
    int oa0_2 = 0, ob0_2 = 0, oa1_2 = 0, ob1_2 = 0;

    decode_basis(2 * tid,                 oa0_0, ob0_0);
    decode_basis(2 * tid + 1,             oa1_0, ob1_0);
    decode_basis(2 * (tid + TPB),         oa0_1, ob0_1);
    decode_basis(2 * (tid + TPB) + 1,     oa1_1, ob1_1);
    if (has2) {
        decode_basis(2 * (tid + 2 * TPB),     oa0_2, ob0_2);
        decode_basis(2 * (tid + 2 * TPB) + 1, oa1_2, ob1_2);
    }

    // Basis coefficients (broadcast, L1-resident).
    const float b00 = Bc[0], b01 = Bc[1], b02 = Bc[2];
    const float b10 = Bc[3], b11 = Bc[4], b12 = Bc[5];
    const float b20 = Bc[6], b21 = Bc[7], b22 = Bc[8];

    // Load rows of x, normalize, evaluate all three polys into shared.
    for (int i = tid; i < RB * D; i += TPB) {
        int r = i / D, d = i - r * D;
        int n = row0 + r;
        float xn = 0.0f;
        if (n < N) xn = (x[(size_t)n * D + d] - mean[d]) / var[d];
        float* p = pv + r * PVR + d;
        p[0 * PVW] = b00 + xn * (b01 + xn * b02);
        p[1 * PVW] = b10 + xn * (b11 + xn * b12);
        p[2 * PVW] = b20 + xn * (b21 + xn * b22);
    }
    __syncthreads();

    // Stream output: fixed bases per thread, loop over rows.
    // Write-through stores: output is write-once / never re-read, so skip the
    // L2 dirty-allocate + eviction round trip and pipeline writes straight out.
    #pragma unroll
    for (int r = 0; r < RB; ++r) {
        if (r >= rows) break;                   // never taken for N=32768
        const float* __restrict__ p = pv + r * PVR;
        float2* __restrict__ orow2 =
            reinterpret_cast<float2*>(out + (size_t)(row0 + r) * NB);

        float2 v0, v1;
        v0.x = p[oa0_0] * p[ob0_0];
        v0.y = p[oa1_0] * p[ob1_0];
        v1.x = p[oa0_1] * p[ob0_1];
        v1.y = p[oa1_1] * p[ob1_1];
        __stwt(orow2 + tid,       v0);
        __stwt(orow2 + tid + TPB, v1);
        if (has2) {
            float2 v2;
            v2.x = p[oa0_2] * p[ob0_2];
            v2.y = p[oa1_2] * p[ob1_2];
            __stwt(orow2 + tid + 2 * TPB, v2);
        }
    }
}

extern "C" void kernel_launch(void* const* d_in, const int* in_sizes, int n_in,
                              void* d_out, int out_size) {
    const float* x      = (const float*)d_in[0];
    const float* mean   = (const float*)d_in[1];
    const float* var    = (const float*)d_in[2];
    const float* oneDb  = (const float*)d_in[3];
    float*       out    = (float*)d_out;

    const int N = in_sizes[0] / D;  // 32768

    int grid = (N + RB - 1) / RB;   // 2048 blocks
    pce_phi_kernel<<<grid, TPB>>>(x, mean, var, oneDb, out, N);
}

// round 15
// speedup vs baseline: 1.1879x; 1.1879x over previous
#include <cuda_runtime.h>
#include <cstdint>

// Problem constants (fixed by the dataset: N=32768, D=50, P=2)
constexpr int D     = 50;
constexpr int NB    = 1326;          // number of basis functions
constexpr int NPAIR = NB / 2;        // 663 : thread handles adjacent bases (2q, 2q+1)
constexpr int TPB   = 256;
constexpr int RB    = 16;            // rows of x per block
constexpr int PVW   = 52;            // padded width of one pv order row
constexpr int PVR   = 3 * PVW;       // floats per row in pv table (156)

// Analytic decode of the reference _indexset(50, p<=2) layout.
// Returns the two pv offsets (order*PVW + dim) for basis b; identity term = 0
// (pv[order 0][dim 0] == B[0,0] == 1.0).
//
// Layout (concat of indexset(50,0), indexset(50,1), indexset(50,2)):
//   b = 0        : zero multi-index
//   b in [1,50]  : order 1 at dim (50 - b)
//   b in [51,..] : k = b-51 indexes indexset(50,2):
//     m* = largest m with T(m)=m(m+1)/2 <= k ; t = 49-m* ; rem = k-T(m*)
//     rem < m*  -> order-1 at dims (t, 49-rem)
//     rem == m* -> order-2 at dim t
__device__ __forceinline__ void decode_basis(int b, int& offA, int& offB) {
    if (b == 0)       { offA = 0;                  offB = 0; return; }
    if (b <= D)       { offA = PVW + (D - b);      offB = 0; return; }
    int k = b - (D + 1);
    int m = (int)((sqrtf(8.0f * (float)k + 1.0f) - 1.0f) * 0.5f);
    while ((m + 1) * (m + 2) / 2 <= k) ++m;   // fixup for sqrt rounding
    while (m * (m + 1) / 2 > k) --m;
    int t   = (D - 1) - m;
    int rem = k - m * (m + 1) / 2;
    if (rem < m) { offA = PVW + t;     offB = PVW + ((D - 1) - rem); }
    else         { offA = 2 * PVW + t; offB = 0; }
}

__global__ __launch_bounds__(TPB)
void pce_phi_kernel(const float* __restrict__ x,
                    const float* __restrict__ mean,
                    const float* __restrict__ var,
                    const float* __restrict__ Bc,   // oneDbasis (3,3) row-major
                    float* __restrict__ out,
                    int N) {
    __shared__ float pv[RB * PVR];   // [row][order][dim], 9984 B

    const int tid  = threadIdx.x;
    const int row0 = blockIdx.x * RB;
    const int rows = min(RB, N - row0);

    // Per-thread basis-pair term offsets, decoded analytically (no global table).
    // Slot 0: q = tid         (always valid)
    // Slot 1: q = tid + 256   (always valid)
    // Slot 2: q = tid + 512   (valid iff tid < 663 - 512 = 151)
    const bool has2 = (tid < NPAIR - 2 * TPB);

    int oa0_0, ob0_0, oa1_0, ob1_0;
    int oa0_1, ob0_1, oa1_1, ob1_1;
    int oa0_2 = 0, ob0_2 = 0, oa1_2 = 0, ob1_2 = 0;

    decode_basis(2 * tid,                 oa0_0, ob0_0);
    decode_basis(2 * tid + 1,             oa1_0, ob1_0);
    decode_basis(2 * (tid + TPB),         oa0_1, ob0_1);
    decode_basis(2 * (tid + TPB) + 1,     oa1_1, ob1_1);
    if (has2) {
        decode_basis(2 * (tid + 2 * TPB),     oa0_2, ob0_2);
        decode_basis(2 * (tid + 2 * TPB) + 1, oa1_2, ob1_2);
    }

    // Basis coefficients (broadcast, L1-resident).
    const float b00 = Bc[0], b01 = Bc[1], b02 = Bc[2];
    const float b10 = Bc[3], b11 = Bc[4], b12 = Bc[5];
    const float b20 = Bc[6], b21 = Bc[7], b22 = Bc[8];

    // Load rows of x, normalize, evaluate all three polys into shared.
    for (int i = tid; i < RB * D; i += TPB) {
        int r = i / D, d = i - r * D;
        int n = row0 + r;
        float xn = 0.0f;
        if (n < N) xn = (x[(size_t)n * D + d] - mean[d]) / var[d];
        float* p = pv + r * PVR + d;
        p[0 * PVW] = b00 + xn * (b01 + xn * b02);
        p[1 * PVW] = b10 + xn * (b11 + xn * b12);
        p[2 * PVW] = b20 + xn * (b21 + xn * b22);
    }
    __syncthreads();

    // Stream output: fixed bases per thread, loop over rows, float2 stcs stores.
    #pragma unroll
    for (int r = 0; r < RB; ++r) {
        if (r >= rows) break;                   // never taken for N=32768
        const float* __restrict__ p = pv + r * PVR;
        float2* __restrict__ orow2 =
            reinterpret_cast<float2*>(out + (size_t)(row0 + r) * NB);

        float2 v0, v1;
        v0.x = p[oa0_0] * p[ob0_0];
        v0.y = p[oa1_0] * p[ob1_0];
        v1.x = p[oa0_1] * p[ob0_1];
        v1.y = p[oa1_1] * p[ob1_1];
        __stcs(orow2 + tid,       v0);
        __stcs(orow2 + tid + TPB, v1);
        if (has2) {
            float2 v2;
            v2.x = p[oa0_2] * p[ob0_2];
            v2.y = p[oa1_2] * p[ob1_2];
            __stcs(orow2 + tid + 2 * TPB, v2);
        }
    }
}

extern "C" void kernel_launch(void* const* d_in, const int* in_sizes, int n_in,
                              void* d_out, int out_size) {
    const float* x      = (const float*)d_in[0];
    const float* mean   = (const float*)d_in[1];
    const float* var    = (const float*)d_in[2];
    const float* oneDb  = (const float*)d_in[3];
    float*       out    = (float*)d_out;

    const int N = in_sizes[0] / D;  // 32768

    int grid = (N + RB - 1) / RB;   // 2048 blocks
    pce_phi_kernel<<<grid, TPB>>>(x, mean, var, oneDb, out, N);
}